// round 9
// baseline (speedup 1.0000x reference)
#include <cuda_runtime.h>

#define BB 16
#define CC 80
#define HH 128
#define WW 128
#define NN 50
#define CANDK 100
#define TPB 512
#define NBATCH 32
#define FBLK 560
#define NBLK (FBLK + NBATCH)    // 592 = 148 SMs * 4 blocks
#define HSZ 1024
#define HEMPTY 0xFFFFFFFFu
#define KARR 1536               // window <= 37x37 = 1369, rounded up
#define TOTAL4 (BB * CC * HH * WW / 4)
#define CHUNK (TPB * 4)         // float4 per chunk = 2048 (32 KB)
#define NCHUNK (TOTAL4 / CHUNK) // 2560 exactly
#define LN2 0.6931471805599453

// Partials (each slot written unconditionally every launch) + counters
// (zero at load; reset by the combining block each launch -> replay-safe).
__device__ double g_focal[FBLK];
__device__ float  g_corr[BB];
__device__ float  g_off[BB];
__device__ float  g_size[BB];
__device__ int    g_npos[BB];
__device__ int    g_done;
__device__ int    g_chunk;

__device__ __forceinline__ float clampp(float x) {
    return fminf(fmaxf(x, 1e-4f), 0.9999f);
}
// p^2 * lg2(1-p): ln2 factored out at the end
__device__ __forceinline__ float nb2(float x) {
    float p = clampp(x);
    return p * p * __log2f(1.0f - p);
}

union SmemU {
    struct { unsigned hkey[HSZ]; unsigned hval[HSZ]; } a;              // 8 KB
    struct {
        unsigned keys_v[KARR];        // value bits (positive floats)
        unsigned short keys_i[KARR];  // flat 14-bit index
        float o0[KARR], o1[KARR], s0[KARR], s1[KARR];  // prefetched preds
    } b;                                                               // ~33 KB
};

__global__ void __launch_bounds__(TPB, 4)
fused_kernel(const float4* __restrict__ cls4,
             const float* __restrict__ cls,
             const float* __restrict__ offp,
             const float* __restrict__ sizep,
             const float* __restrict__ gt_box,
             const int* __restrict__ gt_class,
             float* __restrict__ out) {
    __shared__ SmemU u;
    __shared__ int hist[256];
    __shared__ int wsum[16];
    __shared__ float wsf[16];
    __shared__ double wsd[16];
    __shared__ float s_w[NN], s_h[NN];
    __shared__ int s_ch[NN];
    __shared__ int s_last;
    __shared__ unsigned s_pfx;
    __shared__ int s_kth;
    __shared__ int s_eq;
    __shared__ int s_flag;
    __shared__ int s_chunk;

    const int tid = threadIdx.x;
    const int lane = tid & 31, wrp = tid >> 5;

    if (blockIdx.x >= NBATCH) {
        // ========= focal partial: DYNAMIC chunk stealing (no tail) =========
        double dacc = 0.0;
        if (tid == 0) s_chunk = atomicAdd(&g_chunk, 1);
        __syncthreads();
        int c = s_chunk;
        while (c < NCHUNK) {
            int base = c * CHUNK + tid;
            // issue the 4 independent loads for this chunk immediately
            float4 v0 = cls4[base];
            float4 v1 = cls4[base + TPB];
            float4 v2 = cls4[base + 2 * TPB];
            float4 v3 = cls4[base + 3 * TPB];
            __syncthreads();            // all threads have consumed s_chunk
            if (tid == 0) s_chunk = atomicAdd(&g_chunk, 1);  // prefetch next id
            float a0 = nb2(v0.x) + nb2(v0.y) + nb2(v0.z) + nb2(v0.w);
            float a1 = nb2(v1.x) + nb2(v1.y) + nb2(v1.z) + nb2(v1.w);
            float a2 = nb2(v2.x) + nb2(v2.y) + nb2(v2.z) + nb2(v2.w);
            float a3 = nb2(v3.x) + nb2(v3.y) + nb2(v3.z) + nb2(v3.w);
            dacc += (double)((a0 + a1) + (a2 + a3));  // fixed per-chunk term
            __syncthreads();
            c = s_chunk;
        }
        #pragma unroll
        for (int o = 16; o; o >>= 1)
            dacc += __shfl_down_sync(0xffffffffu, dacc, o);
        if (lane == 0) wsd[wrp] = dacc;
        __syncthreads();
        if (tid == 0) {
            double s = 0.0;
            #pragma unroll
            for (int k = 0; k < 16; k++) s += wsd[k];
            g_focal[blockIdx.x - NBATCH] = s * LN2;
        }
    } else if (blockIdx.x < BB) {
        // ========== type A: gt hash-dedup + focal corrections ==========
        const int b = blockIdx.x;
        const float* clsb = cls + (size_t)b * CC * HH * WW;

        for (int s = tid; s < HSZ; s += TPB) { u.a.hkey[s] = HEMPTY; u.a.hval[s] = 0u; }
        __syncthreads();

        if (tid < NN) {
            int clsv = gt_class[b * NN + tid];
            float4 bx = ((const float4*)gt_box)[b * NN + tid];
            if (clsv != -1) {
                int ch = max(clsv, 0);
                float wv = bx.z - bx.x;
                float hv = bx.w - bx.y;
                int cx = (int)floorf(floorf(wv * 0.5f) * 0.25f);
                int cy = (int)floorf(floorf(hv * 0.5f) * 0.25f);
                const float ONE_V = 0.6065306597126334f;   // exp(-0.5)
                const float TWO_V = 0.36787944117144233f;  // exp(-1.0)
                bool interior = (cx >= 1) && (cy >= 1) && (cx + 1 < HH) && (cy + 1 < WW);
                #pragma unroll
                for (int k = 0; k < 9; k++) {
                    int dx = k / 3 - 1, dy = k % 3 - 1;
                    float vv;
                    if (dx == 0 && dy == 0) {
                        if (cx < 0 || cx >= HH || cy < 0 || cy >= WW) continue;
                        vv = 1.0f;
                    } else {
                        if (!interior) continue;
                        vv = (dx != 0 && dy != 0) ? TWO_V : ONE_V;
                    }
                    unsigned cell = (unsigned)(((ch * HH + cx + dx) * WW) + cy + dy);
                    unsigned slot = (cell * 2654435761u) & (HSZ - 1);
                    while (true) {
                        unsigned prev = atomicCAS(&u.a.hkey[slot], HEMPTY, cell);
                        if (prev == HEMPTY || prev == cell) {
                            atomicMax(&u.a.hval[slot], __float_as_uint(vv));
                            break;
                        }
                        slot = (slot + 1) & (HSZ - 1);
                    }
                }
            }
        }
        __syncthreads();

        float corr = 0.f;
        for (int s = tid; s < HSZ; s += TPB) {
            unsigned cell = u.a.hkey[s];
            if (cell != HEMPTY) {
                float g = __uint_as_float(u.a.hval[s]);
                float p = clampp(clsb[cell]);
                float base = p * p * __logf(1.0f - p);
                float actual;
                if (g == 1.0f) {
                    float q = 1.0f - p, q2 = q * q;
                    actual = q2 * q2 * __logf(p);
                } else {
                    float q = 1.0f - g, q2 = q * q;
                    actual = q2 * q2 * base;
                }
                corr += actual - base;
            }
        }
        #pragma unroll
        for (int o = 16; o; o >>= 1) corr += __shfl_down_sync(0xffffffffu, corr, o);
        if (lane == 0) wsf[wrp] = corr;
        __syncthreads();
        if (tid == 0) {
            float s = 0.f;
            #pragma unroll
            for (int k = 0; k < 16; k++) s += wsf[k];
            g_corr[b] = s;
        }
    } else {
        // ========== type B: top-CANDK select + offset/size loss ==========
        const int b = blockIdx.x - BB;
        const float* clsb = cls + (size_t)b * CC * HH * WW;

        if (tid == 0) s_last = -1;
        __syncthreads();
        if (tid < NN) {
            int clsv = gt_class[b * NN + tid];
            float4 bx = ((const float4*)gt_box)[b * NN + tid];
            s_w[tid] = bx.z - bx.x;
            s_h[tid] = bx.w - bx.y;
            s_ch[tid] = max(clsv, 0);
            if (clsv != -1) atomicMax(&s_last, tid);
        }
        __syncthreads();

        int last = s_last;
        float sO = 0.f, sS = 0.f;
        int K = 0;
        float wv = 0.f, hv = 0.f;
        if (last >= 0) {
            wv = s_w[last];
            hv = s_h[last];
            int ch = s_ch[last];
            int cx = (int)floorf(floorf(wv * 0.5f) * 0.25f);
            int cy = (int)floorf(floorf(hv * 0.5f) * 0.25f);
            int w4 = (int)floorf(wv * 0.25f);
            int h4 = (int)floorf(hv * 0.25f);
            int left   = max((cx - (w4 >> 1)) >> 1, 0);   // >>1 == floor-div 2
            int right  = min((cx + (w4 >> 1)) >> 1, HH / 2);
            int top    = max((cy - (h4 >> 1)) >> 1, 0);
            int bottom = min((cy + (h4 >> 1)) >> 1, WW / 2);
            int wr = right - left, hc = bottom - top;
            int M = (wr > 0 && hc > 0) ? wr * hc : 0;
            M = min(M, KARR);    // guaranteed by input ranges; safety clamp
            K = min(CANDK, M);
            if (M > 0) {
                int Mr = (M + TPB - 1) & ~(TPB - 1);   // <= KARR
                // ONE global phase: window values + off/size prefetch together
                for (int t = tid; t < M; t += TPB) {
                    int r = left + t / hc;
                    int c = top + t % hc;
                    int rc = r * WW + c;
                    float vv = clsb[ch * HH * WW + rc];
                    u.b.keys_v[t] = __float_as_uint(vv);
                    u.b.keys_i[t] = (unsigned short)rc;
                    u.b.o0[t] = offp[(b * 2 + 0) * HH * WW + rc];
                    u.b.o1[t] = offp[(b * 2 + 1) * HH * WW + rc];
                    u.b.s0[t] = sizep[(b * 2 + 0) * HH * WW + rc];
                    u.b.s1[t] = sizep[(b * 2 + 1) * HH * WW + rc];
                }
                for (int t = M + tid; t < Mr; t += TPB) u.b.keys_v[t] = 0xFFFFFFFFu;
                __syncthreads();

                unsigned V = 0xFFFFFFFFu;   // M <= K: select all
                unsigned Ti = 0xFFFFu;      // inclusive index threshold at v==V
                if (M > K) {
                    // ---- 4-pass radix-select of Kth smallest VALUE ----
                    if (tid == 0) { s_pfx = 0u; s_kth = K; }
                    __syncthreads();
                    #pragma unroll
                    for (int pi = 0; pi < 4; pi++) {
                        const int d = 24 - 8 * pi;
                        if (tid < 256) hist[tid] = 0;
                        __syncthreads();
                        unsigned pfx = s_pfx;
                        int kth = s_kth;
                        for (int i = tid; i < Mr; i += TPB) {
                            unsigned v = u.b.keys_v[i];
                            if (pi == 0 || (v >> (d + 8)) == pfx)
                                atomicAdd(&hist[(v >> d) & 255], 1);
                        }
                        __syncthreads();
                        if (tid < 256) {
                            int h0 = hist[tid];
                            int h = h0;
                            #pragma unroll
                            for (int o = 1; o < 32; o <<= 1) {
                                int n = __shfl_up_sync(0xffffffffu, h, o);
                                if (lane >= o) h += n;
                            }
                            if (lane == 31) wsum[wrp] = h;
                            __syncwarp();
                        }
                        __syncthreads();
                        if (tid < 8) {
                            int s = wsum[tid];
                            #pragma unroll
                            for (int o = 1; o < 8; o <<= 1) {
                                int n = __shfl_up_sync(0xffu, s, o);
                                if (tid >= o) s += n;
                            }
                            wsum[tid] = s;
                        }
                        __syncthreads();
                        if (tid < 256) {
                            int h0 = hist[tid];
                            int h = h0;
                            #pragma unroll
                            for (int o = 1; o < 32; o <<= 1) {
                                int n = __shfl_up_sync(0xffffffffu, h, o);
                                if (lane >= o) h += n;
                            }
                            int cum = h + (wrp ? wsum[wrp - 1] : 0);
                            if (cum - h0 < kth && kth <= cum) {   // one thread
                                s_kth = kth - (cum - h0);
                                s_pfx = (pfx << 8) | (unsigned)tid;
                                if (pi == 3) s_eq = h0;
                            }
                        }
                        __syncthreads();
                    }
                    V = s_pfx;
                    int needed = s_kth, eqc = s_eq;
                    if (needed < eqc) {
                        // ---- rare: tie-break on index (2x7-bit radix) ----
                        if (tid == 0) s_pfx = 0u;
                        __syncthreads();
                        #pragma unroll
                        for (int pi = 0; pi < 2; pi++) {
                            const int d = 7 - 7 * pi;
                            if (tid < 128) hist[tid] = 0;
                            __syncthreads();
                            unsigned pfx = s_pfx;
                            int kth = s_kth;
                            for (int i = tid; i < Mr; i += TPB) {
                                if (u.b.keys_v[i] == V) {
                                    unsigned ix = u.b.keys_i[i];
                                    if (pi == 0 || (ix >> (d + 7)) == pfx)
                                        atomicAdd(&hist[(ix >> d) & 127], 1);
                                }
                            }
                            __syncthreads();
                            if (tid < 128) {
                                int h0 = hist[tid];
                                int h = h0;
                                #pragma unroll
                                for (int o = 1; o < 32; o <<= 1) {
                                    int n = __shfl_up_sync(0xffffffffu, h, o);
                                    if (lane >= o) h += n;
                                }
                                if (lane == 31) wsum[wrp] = h;
                                __syncwarp();
                            }
                            __syncthreads();
                            if (tid < 4) {
                                int s = wsum[tid];
                                #pragma unroll
                                for (int o = 1; o < 4; o <<= 1) {
                                    int n = __shfl_up_sync(0xfu, s, o);
                                    if (tid >= o) s += n;
                                }
                                wsum[tid] = s;
                            }
                            __syncthreads();
                            if (tid < 128) {
                                int h0 = hist[tid];
                                int h = h0;
                                #pragma unroll
                                for (int o = 1; o < 32; o <<= 1) {
                                    int n = __shfl_up_sync(0xffffffffu, h, o);
                                    if (lane >= o) h += n;
                                }
                                int cum = h + (wrp ? wsum[wrp - 1] : 0);
                                if (cum - h0 < kth && kth <= cum) {
                                    s_kth = kth - (cum - h0);
                                    s_pfx = (s_pfx << 7) | (unsigned)tid;
                                }
                            }
                            __syncthreads();
                        }
                        Ti = s_pfx;   // include idx <= Ti among v==V
                    }
                }

                float cxf = wv * 0.5f * 0.25f;
                float cyf = hv * 0.5f * 0.25f;
                float off0 = cxf - floorf(cxf);
                float off1 = cyf - floorf(cyf);
                // final accumulation: shared-only (no global gather)
                for (int t = tid; t < M; t += TPB) {
                    unsigned v = u.b.keys_v[t];
                    unsigned ix = u.b.keys_i[t];
                    if (v < V || (v == V && ix <= Ti)) {
                        sO += fabsf(u.b.o0[t] - off0) + fabsf(u.b.o1[t] - off1);
                        sS += fabsf(u.b.s0[t] - wv) + fabsf(u.b.s1[t] - hv);
                    }
                }
            }
        }
        #pragma unroll
        for (int o = 16; o; o >>= 1) {
            sO += __shfl_down_sync(0xffffffffu, sO, o);
            sS += __shfl_down_sync(0xffffffffu, sS, o);
        }
        __syncthreads();
        if (lane == 0) { wsf[wrp] = sO; wsd[wrp] = (double)sS; }
        __syncthreads();
        if (tid == 0) {
            float aO = 0.f, aS = 0.f;
            #pragma unroll
            for (int k = 0; k < 16; k++) { aO += wsf[k]; aS += (float)wsd[k]; }
            g_off[b] = aO;
            g_size[b] = aS;
            g_npos[b] = K;
        }
    }

    // ================= last-block combine =================
    __threadfence();
    __syncthreads();
    if (tid == 0) s_flag = (atomicAdd(&g_done, 1) == NBLK - 1);
    __syncthreads();
    if (s_flag) {
        __threadfence();
        double acc = 0.0;
        for (int i2 = tid; i2 < FBLK; i2 += TPB) acc += g_focal[i2];
        #pragma unroll
        for (int o = 16; o; o >>= 1) acc += __shfl_down_sync(0xffffffffu, acc, o);
        if (lane == 0) wsd[wrp] = acc;
        __syncthreads();
        if (tid == 0) {
            double fsum = 0.0;
            #pragma unroll
            for (int k = 0; k < 16; k++) fsum += wsd[k];
            double corr = 0.0, offs = 0.0, szs = 0.0;
            int npos = 0;
            for (int b2 = 0; b2 < BB; b2++) {
                corr += (double)g_corr[b2];
                offs += (double)g_off[b2];
                szs  += (double)g_size[b2];
                npos += g_npos[b2];
            }
            double np = (double)max(npos, 1);
            double cls_loss = -(fsum + corr) / (double)(BB * HH * WW);
            out[0] = (float)(cls_loss + 0.1 * (szs / np) + (offs / np));
            g_chunk = 0;   // reset for next graph replay
            g_done = 0;
        }
    }
}

extern "C" void kernel_launch(void* const* d_in, const int* in_sizes, int n_in,
                              void* d_out, int out_size) {
    const float* cls_pred    = (const float*)d_in[0];
    const float* offset_pred = (const float*)d_in[1];
    const float* size_pred   = (const float*)d_in[2];
    const float* gt_box      = (const float*)d_in[3];
    const int*   gt_class    = (const int*)d_in[4];
    float* out = (float*)d_out;
    (void)in_sizes; (void)n_in; (void)out_size;

    fused_kernel<<<NBLK, TPB>>>((const float4*)cls_pred, cls_pred,
                                offset_pred, size_pred, gt_box, gt_class, out);
}

// round 10
// speedup vs baseline: 1.0534x; 1.0534x over previous
#include <cuda_runtime.h>
#include <cstdint>

#define BB 16
#define CC 80
#define HH 128
#define WW 128
#define NN 50
#define CANDK 100
#define TPB 512
#define NBATCH 32
#define FBLK 560
#define NBLK (FBLK + NBATCH)    // 592 = 148 SMs * 4 blocks
#define HSZ 1024
#define HEMPTY 0xFFFFFFFFu
#define KARR 1536               // window <= 37x37 = 1369, rounded up
#define TILEF 4096              // floats per tile (16 KB)
#define TILEB (TILEF * 4)
#define NTILE (BB * CC * HH * WW / TILEF)   // 5120 exactly
#define LN2 0.6931471805599453

// Partials (each slot written unconditionally every launch) + done counter
// (zero at load; reset by the combining block each launch -> replay-safe).
__device__ double g_focal[FBLK];
__device__ float  g_corr[BB];
__device__ float  g_off[BB];
__device__ float  g_size[BB];
__device__ int    g_npos[BB];
__device__ int    g_done;

__device__ __forceinline__ float clampp(float x) {
    return fminf(fmaxf(x, 1e-4f), 0.9999f);
}
// p^2 * lg2(1-p): ln2 factored out at the end
__device__ __forceinline__ float nb2(float x) {
    float p = clampp(x);
    return p * p * __log2f(1.0f - p);
}

__device__ __forceinline__ uint32_t smem_u32(const void* p) {
    return (uint32_t)__cvta_generic_to_shared(p);
}

__device__ __forceinline__ void mbar_init(uint32_t mbar, uint32_t cnt) {
    asm volatile("mbarrier.init.shared.b64 [%0], %1;" :: "r"(mbar), "r"(cnt) : "memory");
}
__device__ __forceinline__ void bulk_issue(uint32_t dst, const float* src,
                                           uint32_t bytes, uint32_t mbar) {
    asm volatile("mbarrier.arrive.expect_tx.shared.b64 _, [%0], %1;"
                 :: "r"(mbar), "r"(bytes) : "memory");
    asm volatile("cp.async.bulk.shared::cta.global.mbarrier::complete_tx::bytes "
                 "[%0], [%1], %2, [%3];"
                 :: "r"(dst), "l"(src), "r"(bytes), "r"(mbar) : "memory");
}
__device__ __forceinline__ void mbar_wait(uint32_t mbar, uint32_t parity) {
    uint32_t done;
    asm volatile(
        "{\n\t.reg .pred p;\n\t"
        "mbarrier.try_wait.parity.acquire.cta.shared::cta.b64 p, [%1], %2;\n\t"
        "selp.b32 %0, 1, 0, p;\n\t}"
        : "=r"(done) : "r"(mbar), "r"(parity) : "memory");
    if (!done) {
        asm volatile(
            "{\n\t.reg .pred P1;\n\t"
            "WL_%=:\n\t"
            "mbarrier.try_wait.parity.acquire.cta.shared::cta.b64 P1, [%0], %1, 0x989680;\n\t"
            "@P1 bra.uni WD_%=;\n\t"
            "bra.uni WL_%=;\n\t"
            "WD_%=:\n\t}"
            :: "r"(mbar), "r"(parity) : "memory");
    }
}

union SmemU {
    struct { unsigned hkey[HSZ]; unsigned hval[HSZ]; } a;              // 8 KB
    struct {
        unsigned keys_v[KARR];
        unsigned short keys_i[KARR];
        float o0[KARR], o1[KARR], s0[KARR], s1[KARR];                  // ~33 KB
    } b;
    struct { __align__(128) float buf[2][TILEF]; } f;                  // 32 KB
};

__global__ void __launch_bounds__(TPB, 4)
fused_kernel(const float* __restrict__ cls,
             const float* __restrict__ offp,
             const float* __restrict__ sizep,
             const float* __restrict__ gt_box,
             const int* __restrict__ gt_class,
             float* __restrict__ out) {
    __shared__ SmemU u;
    __shared__ __align__(8) unsigned long long s_mbar[2];
    __shared__ int hist[256];
    __shared__ int wsum[16];
    __shared__ float wsf[16];
    __shared__ double wsd[16];
    __shared__ float s_w[NN], s_h[NN];
    __shared__ int s_ch[NN];
    __shared__ int s_last;
    __shared__ unsigned s_pfx;
    __shared__ int s_kth;
    __shared__ int s_eq;
    __shared__ int s_flag;

    const int tid = threadIdx.x;
    const int lane = tid & 31, wrp = tid >> 5;

    if (blockIdx.x >= NBATCH) {
        // ===== focal partial: cp.async.bulk double-buffered pipeline =====
        const int f = blockIdx.x - NBATCH;
        const int nt = (NTILE - f + FBLK - 1) / FBLK;   // 9 or 10 tiles
        uint32_t mb[2] = { smem_u32(&s_mbar[0]), smem_u32(&s_mbar[1]) };
        uint32_t sb[2] = { smem_u32(&u.f.buf[0][0]), smem_u32(&u.f.buf[1][0]) };
        if (tid == 0) { mbar_init(mb[0], 1); mbar_init(mb[1], 1); }
        __syncthreads();
        asm volatile("fence.proxy.async.shared::cta;" ::: "memory");

        if (tid == 0) bulk_issue(sb[0], cls + (size_t)f * TILEF, TILEB, mb[0]);

        float ph0 = 0;  // (placeholder to keep regs low) -- real phases below
        int phase[2] = {0, 0};
        double dacc = 0.0;
        (void)ph0;
        for (int k = 0; k < nt; k++) {
            int cur = k & 1;
            if (tid == 0 && k + 1 < nt)
                bulk_issue(sb[cur ^ 1],
                           cls + (size_t)(f + (k + 1) * FBLK) * TILEF,
                           TILEB, mb[cur ^ 1]);
            mbar_wait(mb[cur], phase[cur]);
            phase[cur] ^= 1;
            const float4* bp = (const float4*)&u.f.buf[cur][0];
            float4 v0 = bp[tid];
            float4 v1 = bp[tid + TPB];
            float a0 = nb2(v0.x) + nb2(v0.y) + nb2(v0.z) + nb2(v0.w);
            float a1 = nb2(v1.x) + nb2(v1.y) + nb2(v1.z) + nb2(v1.w);
            dacc += (double)(a0 + a1);
            __syncthreads();    // all threads done with buf[cur] before refill
        }
        #pragma unroll
        for (int o = 16; o; o >>= 1)
            dacc += __shfl_down_sync(0xffffffffu, dacc, o);
        if (lane == 0) wsd[wrp] = dacc;
        __syncthreads();
        if (tid == 0) {
            double s = 0.0;
            #pragma unroll
            for (int k = 0; k < 16; k++) s += wsd[k];
            g_focal[f] = s * LN2;
        }
    } else if (blockIdx.x < BB) {
        // ========== type A: gt hash-dedup + focal corrections ==========
        const int b = blockIdx.x;
        const float* clsb = cls + (size_t)b * CC * HH * WW;

        for (int s = tid; s < HSZ; s += TPB) { u.a.hkey[s] = HEMPTY; u.a.hval[s] = 0u; }
        __syncthreads();

        if (tid < NN) {
            int clsv = gt_class[b * NN + tid];
            float4 bx = ((const float4*)gt_box)[b * NN + tid];
            if (clsv != -1) {
                int ch = max(clsv, 0);
                float wv = bx.z - bx.x;
                float hv = bx.w - bx.y;
                int cx = (int)floorf(floorf(wv * 0.5f) * 0.25f);
                int cy = (int)floorf(floorf(hv * 0.5f) * 0.25f);
                const float ONE_V = 0.6065306597126334f;   // exp(-0.5)
                const float TWO_V = 0.36787944117144233f;  // exp(-1.0)
                bool interior = (cx >= 1) && (cy >= 1) && (cx + 1 < HH) && (cy + 1 < WW);
                #pragma unroll
                for (int k = 0; k < 9; k++) {
                    int dx = k / 3 - 1, dy = k % 3 - 1;
                    float vv;
                    if (dx == 0 && dy == 0) {
                        if (cx < 0 || cx >= HH || cy < 0 || cy >= WW) continue;
                        vv = 1.0f;
                    } else {
                        if (!interior) continue;
                        vv = (dx != 0 && dy != 0) ? TWO_V : ONE_V;
                    }
                    unsigned cell = (unsigned)(((ch * HH + cx + dx) * WW) + cy + dy);
                    unsigned slot = (cell * 2654435761u) & (HSZ - 1);
                    while (true) {
                        unsigned prev = atomicCAS(&u.a.hkey[slot], HEMPTY, cell);
                        if (prev == HEMPTY || prev == cell) {
                            atomicMax(&u.a.hval[slot], __float_as_uint(vv));
                            break;
                        }
                        slot = (slot + 1) & (HSZ - 1);
                    }
                }
            }
        }
        __syncthreads();

        float corr = 0.f;
        for (int s = tid; s < HSZ; s += TPB) {
            unsigned cell = u.a.hkey[s];
            if (cell != HEMPTY) {
                float g = __uint_as_float(u.a.hval[s]);
                float p = clampp(clsb[cell]);
                float base = p * p * __logf(1.0f - p);
                float actual;
                if (g == 1.0f) {
                    float q = 1.0f - p, q2 = q * q;
                    actual = q2 * q2 * __logf(p);
                } else {
                    float q = 1.0f - g, q2 = q * q;
                    actual = q2 * q2 * base;
                }
                corr += actual - base;
            }
        }
        #pragma unroll
        for (int o = 16; o; o >>= 1) corr += __shfl_down_sync(0xffffffffu, corr, o);
        if (lane == 0) wsf[wrp] = corr;
        __syncthreads();
        if (tid == 0) {
            float s = 0.f;
            #pragma unroll
            for (int k = 0; k < 16; k++) s += wsf[k];
            g_corr[b] = s;
        }
    } else {
        // ========== type B: top-CANDK select + offset/size loss ==========
        const int b = blockIdx.x - BB;
        const float* clsb = cls + (size_t)b * CC * HH * WW;

        if (tid == 0) s_last = -1;
        __syncthreads();
        if (tid < NN) {
            int clsv = gt_class[b * NN + tid];
            float4 bx = ((const float4*)gt_box)[b * NN + tid];
            s_w[tid] = bx.z - bx.x;
            s_h[tid] = bx.w - bx.y;
            s_ch[tid] = max(clsv, 0);
            if (clsv != -1) atomicMax(&s_last, tid);
        }
        __syncthreads();

        int last = s_last;
        float sO = 0.f, sS = 0.f;
        int K = 0;
        float wv = 0.f, hv = 0.f;
        if (last >= 0) {
            wv = s_w[last];
            hv = s_h[last];
            int ch = s_ch[last];
            int cx = (int)floorf(floorf(wv * 0.5f) * 0.25f);
            int cy = (int)floorf(floorf(hv * 0.5f) * 0.25f);
            int w4 = (int)floorf(wv * 0.25f);
            int h4 = (int)floorf(hv * 0.25f);
            int left   = max((cx - (w4 >> 1)) >> 1, 0);   // >>1 == floor-div 2
            int right  = min((cx + (w4 >> 1)) >> 1, HH / 2);
            int top    = max((cy - (h4 >> 1)) >> 1, 0);
            int bottom = min((cy + (h4 >> 1)) >> 1, WW / 2);
            int wr = right - left, hc = bottom - top;
            int M = (wr > 0 && hc > 0) ? wr * hc : 0;
            M = min(M, KARR);    // guaranteed by input ranges; safety clamp
            K = min(CANDK, M);
            if (M > 0) {
                int Mr = (M + TPB - 1) & ~(TPB - 1);   // <= KARR
                // ONE global phase: window values + off/size prefetch together
                for (int t = tid; t < M; t += TPB) {
                    int r = left + t / hc;
                    int c = top + t % hc;
                    int rc = r * WW + c;
                    float vv = clsb[ch * HH * WW + rc];
                    u.b.keys_v[t] = __float_as_uint(vv);
                    u.b.keys_i[t] = (unsigned short)rc;
                    u.b.o0[t] = offp[(b * 2 + 0) * HH * WW + rc];
                    u.b.o1[t] = offp[(b * 2 + 1) * HH * WW + rc];
                    u.b.s0[t] = sizep[(b * 2 + 0) * HH * WW + rc];
                    u.b.s1[t] = sizep[(b * 2 + 1) * HH * WW + rc];
                }
                for (int t = M + tid; t < Mr; t += TPB) u.b.keys_v[t] = 0xFFFFFFFFu;
                __syncthreads();

                unsigned V = 0xFFFFFFFFu;   // M <= K: select all
                unsigned Ti = 0xFFFFu;      // inclusive index threshold at v==V
                if (M > K) {
                    // ---- 4-pass radix-select of Kth smallest VALUE ----
                    if (tid == 0) { s_pfx = 0u; s_kth = K; }
                    __syncthreads();
                    #pragma unroll
                    for (int pi = 0; pi < 4; pi++) {
                        const int d = 24 - 8 * pi;
                        if (tid < 256) hist[tid] = 0;
                        __syncthreads();
                        unsigned pfx = s_pfx;
                        int kth = s_kth;
                        for (int i = tid; i < Mr; i += TPB) {
                            unsigned v = u.b.keys_v[i];
                            if (pi == 0 || (v >> (d + 8)) == pfx)
                                atomicAdd(&hist[(v >> d) & 255], 1);
                        }
                        __syncthreads();
                        if (tid < 256) {
                            int h0 = hist[tid];
                            int h = h0;
                            #pragma unroll
                            for (int o = 1; o < 32; o <<= 1) {
                                int n = __shfl_up_sync(0xffffffffu, h, o);
                                if (lane >= o) h += n;
                            }
                            if (lane == 31) wsum[wrp] = h;
                            __syncwarp();
                        }
                        __syncthreads();
                        if (tid < 8) {
                            int s = wsum[tid];
                            #pragma unroll
                            for (int o = 1; o < 8; o <<= 1) {
                                int n = __shfl_up_sync(0xffu, s, o);
                                if (tid >= o) s += n;
                            }
                            wsum[tid] = s;
                        }
                        __syncthreads();
                        if (tid < 256) {
                            int h0 = hist[tid];
                            int h = h0;
                            #pragma unroll
                            for (int o = 1; o < 32; o <<= 1) {
                                int n = __shfl_up_sync(0xffffffffu, h, o);
                                if (lane >= o) h += n;
                            }
                            int cum = h + (wrp ? wsum[wrp - 1] : 0);
                            if (cum - h0 < kth && kth <= cum) {   // one thread
                                s_kth = kth - (cum - h0);
                                s_pfx = (pfx << 8) | (unsigned)tid;
                                if (pi == 3) s_eq = h0;
                            }
                        }
                        __syncthreads();
                    }
                    V = s_pfx;
                    int needed = s_kth, eqc = s_eq;
                    if (needed < eqc) {
                        // ---- rare: tie-break on index (2x7-bit radix) ----
                        if (tid == 0) s_pfx = 0u;
                        __syncthreads();
                        #pragma unroll
                        for (int pi = 0; pi < 2; pi++) {
                            const int d = 7 - 7 * pi;
                            if (tid < 128) hist[tid] = 0;
                            __syncthreads();
                            unsigned pfx = s_pfx;
                            int kth = s_kth;
                            for (int i = tid; i < Mr; i += TPB) {
                                if (u.b.keys_v[i] == V) {
                                    unsigned ix = u.b.keys_i[i];
                                    if (pi == 0 || (ix >> (d + 7)) == pfx)
                                        atomicAdd(&hist[(ix >> d) & 127], 1);
                                }
                            }
                            __syncthreads();
                            if (tid < 128) {
                                int h0 = hist[tid];
                                int h = h0;
                                #pragma unroll
                                for (int o = 1; o < 32; o <<= 1) {
                                    int n = __shfl_up_sync(0xffffffffu, h, o);
                                    if (lane >= o) h += n;
                                }
                                if (lane == 31) wsum[wrp] = h;
                                __syncwarp();
                            }
                            __syncthreads();
                            if (tid < 4) {
                                int s = wsum[tid];
                                #pragma unroll
                                for (int o = 1; o < 4; o <<= 1) {
                                    int n = __shfl_up_sync(0xfu, s, o);
                                    if (tid >= o) s += n;
                                }
                                wsum[tid] = s;
                            }
                            __syncthreads();
                            if (tid < 128) {
                                int h0 = hist[tid];
                                int h = h0;
                                #pragma unroll
                                for (int o = 1; o < 32; o <<= 1) {
                                    int n = __shfl_up_sync(0xffffffffu, h, o);
                                    if (lane >= o) h += n;
                                }
                                int cum = h + (wrp ? wsum[wrp - 1] : 0);
                                if (cum - h0 < kth && kth <= cum) {
                                    s_kth = kth - (cum - h0);
                                    s_pfx = (s_pfx << 7) | (unsigned)tid;
                                }
                            }
                            __syncthreads();
                        }
                        Ti = s_pfx;   // include idx <= Ti among v==V
                    }
                }

                float cxf = wv * 0.5f * 0.25f;
                float cyf = hv * 0.5f * 0.25f;
                float off0 = cxf - floorf(cxf);
                float off1 = cyf - floorf(cyf);
                // final accumulation: shared-only (no global gather)
                for (int t = tid; t < M; t += TPB) {
                    unsigned v = u.b.keys_v[t];
                    unsigned ix = u.b.keys_i[t];
                    if (v < V || (v == V && ix <= Ti)) {
                        sO += fabsf(u.b.o0[t] - off0) + fabsf(u.b.o1[t] - off1);
                        sS += fabsf(u.b.s0[t] - wv) + fabsf(u.b.s1[t] - hv);
                    }
                }
            }
        }
        #pragma unroll
        for (int o = 16; o; o >>= 1) {
            sO += __shfl_down_sync(0xffffffffu, sO, o);
            sS += __shfl_down_sync(0xffffffffu, sS, o);
        }
        __syncthreads();
        if (lane == 0) { wsf[wrp] = sO; wsd[wrp] = (double)sS; }
        __syncthreads();
        if (tid == 0) {
            float aO = 0.f, aS = 0.f;
            #pragma unroll
            for (int k = 0; k < 16; k++) { aO += wsf[k]; aS += (float)wsd[k]; }
            g_off[b] = aO;
            g_size[b] = aS;
            g_npos[b] = K;
        }
    }

    // ================= last-block combine =================
    __threadfence();
    __syncthreads();
    if (tid == 0) s_flag = (atomicAdd(&g_done, 1) == NBLK - 1);
    __syncthreads();
    if (s_flag) {
        __threadfence();
        double acc = 0.0;
        for (int i2 = tid; i2 < FBLK; i2 += TPB) acc += g_focal[i2];
        #pragma unroll
        for (int o = 16; o; o >>= 1) acc += __shfl_down_sync(0xffffffffu, acc, o);
        if (lane == 0) wsd[wrp] = acc;
        __syncthreads();
        if (tid == 0) {
            double fsum = 0.0;
            #pragma unroll
            for (int k = 0; k < 16; k++) fsum += wsd[k];
            double corr = 0.0, offs = 0.0, szs = 0.0;
            int npos = 0;
            for (int b2 = 0; b2 < BB; b2++) {
                corr += (double)g_corr[b2];
                offs += (double)g_off[b2];
                szs  += (double)g_size[b2];
                npos += g_npos[b2];
            }
            double np = (double)max(npos, 1);
            double cls_loss = -(fsum + corr) / (double)(BB * HH * WW);
            out[0] = (float)(cls_loss + 0.1 * (szs / np) + (offs / np));
            g_done = 0;   // reset for next graph replay
        }
    }
}

extern "C" void kernel_launch(void* const* d_in, const int* in_sizes, int n_in,
                              void* d_out, int out_size) {
    const float* cls_pred    = (const float*)d_in[0];
    const float* offset_pred = (const float*)d_in[1];
    const float* size_pred   = (const float*)d_in[2];
    const float* gt_box      = (const float*)d_in[3];
    const int*   gt_class    = (const int*)d_in[4];
    float* out = (float*)d_out;
    (void)in_sizes; (void)n_in; (void)out_size;

    fused_kernel<<<NBLK, TPB>>>(cls_pred, offset_pred, size_pred,
                                gt_box, gt_class, out);
}